// round 16
// baseline (speedup 1.0000x reference)
#include <cuda_runtime.h>
#include <cuda_bf16.h>
#include <cstdint>

// Problem constants
#define B_   2
#define INC_ 64
#define OUTC_ 128
#define NP_  8
#define D_   12
#define H_   48
#define W_   48
#define HW_   (H_*W_)        // 2304
#define DHW_  (D_*HW_)       // 27648
#define OFFC_ (3*NP_)        // 24
#define REDN_ (B_*DHW_)      // 55296
#define POSBLK_ 128
#define NBLK_MAIN_ (B_*D_*(HW_/POSBLK_))   // 432

// Scratch (device globals; no allocations allowed)
__device__ float g_offset[B_*OFFC_*DHW_];            // ~5.3 MB
__device__ float g_out[B_*OUTC_*DHW_];               // ~28.3 MB
__device__ __nv_bfloat16 g_wtb_hi[NP_*INC_*OUTC_];   // [nn][c][oc] bf16 hi
__device__ __nv_bfloat16 g_wtb_lo[NP_*INC_*OUTC_];   // [nn][c][oc] bf16 lo
__device__ float g_wp[INC_*27*OFFC_];                // w_p -> [c][k][oc]
__device__ float g_xt[B_*DHW_*INC_];                 // x channel-last [b][dhw][c]
__device__ float g_part[NBLK_MAIN_*OUTC_];
__device__ float g_part2[NBLK_MAIN_*OUTC_];
__device__ float g_mean[OUTC_];
__device__ float g_rstd[OUTC_];

// _p_n(8): base=3, dep=2, row=1, mod=2
__device__ __constant__ float c_pnz[8] = {0,0,0,1,1,1,2,2};
__device__ __constant__ float c_pnx[8] = {0,0,0,0,0,0,1,1};
__device__ __constant__ float c_pny[8] = {0,1,2,0,1,2,0,1};

// ---------------- f32x2 helpers (offset conv: FFMA2, fp32-exact) ----------------
typedef unsigned long long u64;

__device__ __forceinline__ void ffma2(u64 &d, u64 a, u64 b) {
    asm("fma.rn.f32x2 %0, %1, %2, %0;" : "+l"(d) : "l"(a), "l"(b));
}
__device__ __forceinline__ u64 dup2(float x) {
    u64 r; asm("mov.b64 %0, {%1, %1};" : "=l"(r) : "f"(x)); return r;
}
__device__ __forceinline__ u64 pack2(float lo, float hi) {
    u64 r; asm("mov.b64 %0, {%1, %2};" : "=l"(r) : "f"(lo), "f"(hi)); return r;
}
__device__ __forceinline__ float lo32(u64 v){ return __uint_as_float((unsigned int)v); }
__device__ __forceinline__ float hi32(u64 v){ return __uint_as_float((unsigned int)(v >> 32)); }

// ---------------- mma.sync helpers (baseline sm_80+ ISA) ----------------
__device__ __forceinline__ uint32_t smem_u32(const void* p) {
    uint32_t a;
    asm("{ .reg .u64 t; cvta.to.shared.u64 t, %1; cvt.u32.u64 %0, t; }" : "=r"(a) : "l"(p));
    return a;
}
#define LDSM_X4(r0,r1,r2,r3, addr) \
    asm volatile("ldmatrix.sync.aligned.m8n8.x4.shared.b16 {%0,%1,%2,%3}, [%4];" \
        : "=r"(r0),"=r"(r1),"=r"(r2),"=r"(r3) : "r"(addr))
#define LDSM_X4T(r0,r1,r2,r3, addr) \
    asm volatile("ldmatrix.sync.aligned.m8n8.x4.trans.shared.b16 {%0,%1,%2,%3}, [%4];" \
        : "=r"(r0),"=r"(r1),"=r"(r2),"=r"(r3) : "r"(addr))
#define MMA_BF16(c, a0,a1,a2,a3, b0,b1) \
    asm volatile("mma.sync.aligned.m16n8k16.row.col.f32.bf16.bf16.f32 " \
        "{%0,%1,%2,%3}, {%4,%5,%6,%7}, {%8,%9}, {%0,%1,%2,%3};" \
        : "+f"((c)[0]),"+f"((c)[1]),"+f"((c)[2]),"+f"((c)[3]) \
        : "r"(a0),"r"(a1),"r"(a2),"r"(a3), "r"(b0),"r"(b1))

// SMEM layout for k_main (dynamic): total 104448 B
#define SM_IDX   0
#define SM_GWT   16384
#define SM_A_HI  32768
#define SM_A_LO  51200
#define SM_B_HI  69632
#define SM_B_LO  87040
#define SMEM_MAIN_ 104448
#define A_STRIDE_B 144
#define B_STRIDE_B 272

// ---------------------------------------------------------------------------
// Kernel 0: w_p [oc][c][k27] -> g_wp [c][k27][oc24]  (needed by offset conv)
// ---------------------------------------------------------------------------
__global__ void k_wp(const float* __restrict__ w_p) {
    int idx = blockIdx.x * 256 + threadIdx.x;      // 41472 total
    if (idx >= INC_*27*OFFC_) return;
    int k  = idx % 27;
    int c  = (idx / 27) % INC_;
    int oc = idx / (27*INC_);
    g_wp[(c*27 + k)*OFFC_ + oc] = w_p[idx];
}

// ---------------------------------------------------------------------------
// Kernel BIG (merged, overlap): blocks [0,288)     = offset conv (R9 fp32 body)
//                               blocks [288,1152)  = x transpose (channel-last)
//                               blocks [1152,1408) = w_conv bf16 hi/lo split
// The light transpose/split blocks fill the SM slots the 288-block offset
// grid leaves idle (offset caps at ~2 blocks/SM).
// ---------------------------------------------------------------------------
__global__ void __launch_bounds__(288) k_big(
    const float* __restrict__ x,
    const float* __restrict__ b_p,
    const float* __restrict__ w_conv)
{
    __shared__ float sp[12672];          // offset: x_s[7488]+w_s[5184]; xt: tile[64*65]
    const int blk = blockIdx.x;
    const int tid = threadIdx.x;

    if (blk < 288) {
        // ================= offset conv (EXACT R9 body, fp32 FFMA2) =================
        float* x_s = sp;                 // [8][3][6][52]
        float* w_s = sp + 7488;          // [8][27][24]
        const int hblk = blk % (H_/4);
        const int d = (blk / (H_/4)) % D_;
        const int b = blk / ((H_/4)*D_);
        const int h0 = hblk * 4;
        const int hh  = tid / 72;
        const int r   = tid % 72;
        const int ocg = r / 12;
        const int wq  = r % 12;

        const int combo = tid >> 1;
        const int halfS = tid & 1;
        const int sc  = combo / 18;
        const int srw = combo % 18;
        const int sdz = srw / 6;
        const int sdh = srw % 6;
        const int sgd = d + sdz - 1;
        const int sgh = h0 + sdh - 1;
        const bool rowok = ((unsigned)sgd < (unsigned)D_) && ((unsigned)sgh < (unsigned)H_);
        const int srowbase = combo * 52 + halfS * 26;
        const int wl0 = halfS * 26;

        u64 acc[2][4];
        {
            u64 p0 = pack2(__ldg(&b_p[ocg*4+0]), __ldg(&b_p[ocg*4+1]));
            u64 p1 = pack2(__ldg(&b_p[ocg*4+2]), __ldg(&b_p[ocg*4+3]));
            #pragma unroll
            for (int i = 0; i < 4; i++) { acc[0][i] = p0; acc[1][i] = p1; }
        }

        for (int cc = 0; cc < 8; cc++) {
            __syncthreads();
            {
                const float* xrow = x + ((size_t)(b*INC_ + cc*8 + sc)*D_ + (rowok ? sgd : 0))*HW_
                                      + (rowok ? sgh : 0)*W_;
                if (rowok) {
                    #pragma unroll 13
                    for (int j = 0; j < 26; j++) {
                        const int gw = wl0 + j - 1;
                        x_s[srowbase + j] = ((unsigned)gw < (unsigned)W_) ? xrow[gw] : 0.f;
                    }
                } else {
                    #pragma unroll 13
                    for (int j = 0; j < 26; j++) x_s[srowbase + j] = 0.f;
                }
            }
            {
                const float4* src = reinterpret_cast<const float4*>(g_wp + cc*5184);
                float4* dst = reinterpret_cast<float4*>(w_s);
                for (int i = tid; i < 1296; i += 288) dst[i] = __ldg(&src[i]);
            }
            __syncthreads();

            #pragma unroll 2
            for (int c = 0; c < 8; c++) {
                #pragma unroll
                for (int kz = 0; kz < 3; kz++)
                #pragma unroll
                for (int kx = 0; kx < 3; kx++) {
                    const float* xb = &x_s[((c*3 + kz)*6 + hh + kx)*52 + wq*4];
                    float4 xa = *reinterpret_cast<const float4*>(xb);
                    float2 xc = *reinterpret_cast<const float2*>(xb + 4);
                    u64 X[6] = { dup2(xa.x), dup2(xa.y), dup2(xa.z),
                                 dup2(xa.w), dup2(xc.x), dup2(xc.y) };
                    #pragma unroll
                    for (int ky = 0; ky < 3; ky++) {
                        ulonglong2 Wv = *reinterpret_cast<const ulonglong2*>(
                            &w_s[(c*27 + kz*9 + kx*3 + ky)*24 + ocg*4]);
                        #pragma unroll
                        for (int i = 0; i < 4; i++) {
                            ffma2(acc[0][i], Wv.x, X[ky + i]);
                            ffma2(acc[1][i], Wv.y, X[ky + i]);
                        }
                    }
                }
            }
        }

        const int h = h0 + hh;
        #pragma unroll
        for (int p = 0; p < 2; p++) {
            float4 vl = make_float4(lo32(acc[p][0]), lo32(acc[p][1]),
                                    lo32(acc[p][2]), lo32(acc[p][3]));
            float4 vh = make_float4(hi32(acc[p][0]), hi32(acc[p][1]),
                                    hi32(acc[p][2]), hi32(acc[p][3]));
            int oc0 = ocg*4 + p*2;
            *reinterpret_cast<float4*>(
                &g_offset[((b*OFFC_ + oc0    )*D_ + d)*HW_ + h*W_ + wq*4]) = vl;
            *reinterpret_cast<float4*>(
                &g_offset[((b*OFFC_ + oc0 + 1)*D_ + d)*HW_ + h*W_ + wq*4]) = vh;
        }
    } else if (blk < 288 + 864) {
        // ================= x transpose (channel-last) =================
        float* tile = sp;                // [64][65]
        const int bid = blk - 288;
        const int b = bid / (DHW_/64);
        const int p0 = (bid % (DHW_/64)) * 64;
        for (int idx = tid; idx < 4096; idx += 288) {
            int c = idx >> 6, p = idx & 63;
            tile[c*65 + p] = x[(b*INC_ + c)*DHW_ + p0 + p];
        }
        __syncthreads();
        for (int idx = tid; idx < 4096; idx += 288) {
            int p = idx >> 6, c = idx & 63;
            g_xt[(b*DHW_ + p0 + p)*INC_ + c] = tile[c*65 + p];
        }
    } else {
        // ================= w_conv bf16 hi/lo split =================
        if (tid < 256) {
            int idx = (blk - 1152) * 256 + tid;     // 65536 total
            int nn = idx & 7;
            int c  = (idx >> 3) & 63;
            int o  = idx >> 9;
            float w = w_conv[idx];
            __nv_bfloat16 h = __float2bfloat16(w);
            __nv_bfloat16 l = __float2bfloat16(w - __bfloat162float(h));
            g_wtb_hi[(nn*INC_ + c)*OUTC_ + o] = h;
            g_wtb_lo[(nn*INC_ + c)*OUTC_ + o] = l;
        }
    }
}

// ---------------------------------------------------------------------------
// Kernel 2: deformable gather + bf16 3-term mma.sync GEMM (EXACT R14 version).
// ---------------------------------------------------------------------------
__global__ void __launch_bounds__(256) k_main()
{
    extern __shared__ unsigned char smraw[];
    int*   idx_s = (int*)(smraw + SM_IDX);
    float* gwt_s = (float*)(smraw + SM_GWT);
    const uint32_t smb = smem_u32(smraw);

    const int bid = blockIdx.x;
    const int p0   = (bid % (HW_/POSBLK_)) * POSBLK_;
    const int slab = bid / (HW_/POSBLK_);
    const int d = slab % D_;
    const int b = slab / D_;
    const int tid = threadIdx.x;
    const int lane = tid & 31;
    const int wid  = tid >> 5;

    const int bD = b * DHW_;
    #pragma unroll
    for (int i = 0; i < 4; i++) {
        const int q = tid + 256*i;
        const int p = q & 127;
        const int n = q >> 7;
        const int pos = p0 + p;
        const int h = pos / W_;
        const int w = pos % W_;
        const int off_base = (b*OFFC_*D_ + d)*HW_ + pos;
        const float oz = g_offset[off_base + (n       )*DHW_];
        const float ox = g_offset[off_base + (NP_  + n)*DHW_];
        const float oy = g_offset[off_base + (2*NP_+ n)*DHW_];

        const float pz = oz + (float)d + c_pnz[n];
        const float px = ox + (float)h + c_pnx[n];
        const float py = oy + (float)w + c_pny[n];

        const float fz = floorf(pz), fx = floorf(px), fy = floorf(py);
        const float z0f = fminf(fmaxf(fz,       0.f), (float)(D_-1));
        const float z1f = fminf(fmaxf(fz + 1.f, 0.f), (float)(D_-1));
        const float x0f = fminf(fmaxf(fx,       0.f), (float)(H_-1));
        const float x1f = fminf(fmaxf(fx + 1.f, 0.f), (float)(H_-1));
        const float y0f = fminf(fmaxf(fy,       0.f), (float)(W_-1));
        const float y1f = fminf(fmaxf(fy + 1.f, 0.f), (float)(W_-1));
        const float pzc = fminf(fmaxf(pz, 0.f), (float)(D_-1));
        const float pxc = fminf(fmaxf(px, 0.f), (float)(H_-1));
        const float pyc = fminf(fmaxf(py, 0.f), (float)(W_-1));

        const float az = 1.f + (z0f - pzc), bz = 1.f - (z1f - pzc);
        const float ax = 1.f + (x0f - pxc), bx = 1.f - (x1f - pxc);
        const float ay = 1.f + (y0f - pyc), by = 1.f - (y1f - pyc);

        const int z0 = (int)z0f, z1 = (int)z1f;
        const int x0 = (int)x0f, x1 = (int)x1f;
        const int y0 = (int)y0f, y1 = (int)y1f;

        idx_s[q*4+0] = (bD + z0*HW_ + x0*W_ + y0)*INC_;
        idx_s[q*4+1] = (bD + z1*HW_ + x1*W_ + y1)*INC_;
        idx_s[q*4+2] = (bD + z0*HW_ + x1*W_ + y0)*INC_;
        idx_s[q*4+3] = (bD + z1*HW_ + x0*W_ + y1)*INC_;
        gwt_s[q*4+0] = az*ax*ay;
        gwt_s[q*4+1] = bz*bx*by;
        gwt_s[q*4+2] = az*bx*ay;
        gwt_s[q*4+3] = bz*ax*by;
    }

    float acc[16][4];
    #pragma unroll
    for (int t = 0; t < 16; t++)
        #pragma unroll
        for (int j = 0; j < 4; j++) acc[t][j] = 0.f;

    const int f    = lane & 15;
    const int half = lane >> 4;

    const uint32_t aRowOff = (uint32_t)((wid*16 + (lane & 15))*A_STRIDE_B
                                        + ((lane >> 4) << 3)*2);
    const int bKrow = (((lane >> 3) & 1) << 3) + (lane & 7);
    const int bNcol = (lane >> 4) << 3;

    for (int nn = 0; nn < 8; nn++) {
        __syncthreads();
        {
            const uint2* srcH = reinterpret_cast<const uint2*>(g_wtb_hi + nn*8192);
            const uint2* srcL = reinterpret_cast<const uint2*>(g_wtb_lo + nn*8192);
            #pragma unroll
            for (int j = 0; j < 8; j++) {
                const int q = tid + 256*j;
                const int c  = q >> 5;
                const int oq = q & 31;
                *reinterpret_cast<uint2*>(smraw + SM_B_HI + c*B_STRIDE_B + oq*8) = __ldg(&srcH[q]);
                *reinterpret_cast<uint2*>(smraw + SM_B_LO + c*B_STRIDE_B + oq*8) = __ldg(&srcL[q]);
            }
        }
        #pragma unroll 8
        for (int pp = 0; pp < 16; pp++) {
            const int p = wid*16 + pp;
            const int q4 = ((nn << 7) + p) << 2;
            const int   i0 = idx_s[q4 + half];
            const float g0 = gwt_s[q4 + half];
            const int   i1 = idx_s[q4 + half + 2];
            const float g1 = gwt_s[q4 + half + 2];
            const float4 v0 = __ldg((const float4*)(g_xt + i0 + 4*f));
            const float4 v1 = __ldg((const float4*)(g_xt + i1 + 4*f));
            float4 rv;
            rv.x = g0*v0.x + g1*v1.x;
            rv.y = g0*v0.y + g1*v1.y;
            rv.z = g0*v0.z + g1*v1.z;
            rv.w = g0*v0.w + g1*v1.w;
            rv.x += __shfl_xor_sync(0xffffffffu, rv.x, 16);
            rv.y += __shfl_xor_sync(0xffffffffu, rv.y, 16);
            rv.z += __shfl_xor_sync(0xffffffffu, rv.z, 16);
            rv.w += __shfl_xor_sync(0xffffffffu, rv.w, 16);
            if (half == 0) {
                __nv_bfloat16 hx = __float2bfloat16(rv.x);
                __nv_bfloat16 hy = __float2bfloat16(rv.y);
                __nv_bfloat16 hz = __float2bfloat16(rv.z);
                __nv_bfloat16 hw = __float2bfloat16(rv.w);
                __nv_bfloat16 lx = __float2bfloat16(rv.x - __bfloat162float(hx));
                __nv_bfloat16 ly = __float2bfloat16(rv.y - __bfloat162float(hy));
                __nv_bfloat16 lz = __float2bfloat16(rv.z - __bfloat162float(hz));
                __nv_bfloat16 lw = __float2bfloat16(rv.w - __bfloat162float(hw));
                uint2 hv, lv;
                hv.x = ((uint32_t)__bfloat16_as_ushort(hy) << 16) | __bfloat16_as_ushort(hx);
                hv.y = ((uint32_t)__bfloat16_as_ushort(hw) << 16) | __bfloat16_as_ushort(hz);
                lv.x = ((uint32_t)__bfloat16_as_ushort(ly) << 16) | __bfloat16_as_ushort(lx);
                lv.y = ((uint32_t)__bfloat16_as_ushort(lw) << 16) | __bfloat16_as_ushort(lz);
                *reinterpret_cast<uint2*>(smraw + SM_A_HI + p*A_STRIDE_B + 8*f) = hv;
                *reinterpret_cast<uint2*>(smraw + SM_A_LO + p*A_STRIDE_B + 8*f) = lv;
            }
        }
        __syncthreads();

        #pragma unroll
        for (int kk = 0; kk < 4; kk++) {
            uint32_t ah0,ah1,ah2,ah3, al0,al1,al2,al3;
            const uint32_t aAddr = smb + SM_A_HI + aRowOff + (uint32_t)(kk*32);
            LDSM_X4(ah0,ah1,ah2,ah3, aAddr);
            LDSM_X4(al0,al1,al2,al3, aAddr + (SM_A_LO - SM_A_HI));
            #pragma unroll
            for (int ng = 0; ng < 8; ng++) {
                uint32_t bh0,bh1,bh2,bh3, bl0,bl1,bl2,bl3;
                const uint32_t bAddr = smb + SM_B_HI
                    + (uint32_t)((kk*16 + bKrow)*B_STRIDE_B + (ng*16 + bNcol)*2);
                LDSM_X4T(bh0,bh1,bh2,bh3, bAddr);
                LDSM_X4T(bl0,bl1,bl2,bl3, bAddr + (SM_B_LO - SM_B_HI));
                MMA_BF16(acc[2*ng  ], ah0,ah1,ah2,ah3, bh0,bh1);
                MMA_BF16(acc[2*ng+1], ah0,ah1,ah2,ah3, bh2,bh3);
                MMA_BF16(acc[2*ng  ], al0,al1,al2,al3, bh0,bh1);
                MMA_BF16(acc[2*ng+1], al0,al1,al2,al3, bh2,bh3);
                MMA_BF16(acc[2*ng  ], ah0,ah1,ah2,ah3, bl0,bl1);
                MMA_BF16(acc[2*ng+1], ah0,ah1,ah2,ah3, bl2,bl3);
            }
        }
    }

    float* partS = (float*)(smraw);
    float* partQ = (float*)(smraw + 4096);
    const int pos_lo = p0 + wid*16 + (lane >> 2);
    #pragma unroll
    for (int j = 0; j < 16; j++) {
        const int oc0 = j*8 + (lane & 3)*2;
        const float c0 = acc[j][0], c1 = acc[j][1], c2 = acc[j][2], c3 = acc[j][3];
        g_out[((b*OUTC_ + oc0    )*D_ + d)*HW_ + pos_lo    ] = c0;
        g_out[((b*OUTC_ + oc0 + 1)*D_ + d)*HW_ + pos_lo    ] = c1;
        g_out[((b*OUTC_ + oc0    )*D_ + d)*HW_ + pos_lo + 8] = c2;
        g_out[((b*OUTC_ + oc0 + 1)*D_ + d)*HW_ + pos_lo + 8] = c3;
        float s0 = c0 + c2, s1 = c1 + c3;
        float q0 = c0*c0 + c2*c2, q1 = c1*c1 + c3*c3;
        #pragma unroll
        for (int st = 4; st < 32; st <<= 1) {
            s0 += __shfl_xor_sync(0xffffffffu, s0, st);
            s1 += __shfl_xor_sync(0xffffffffu, s1, st);
            q0 += __shfl_xor_sync(0xffffffffu, q0, st);
            q1 += __shfl_xor_sync(0xffffffffu, q1, st);
        }
        if ((lane >> 2) == 0) {
            partS[(oc0    )*8 + wid] = s0;
            partS[(oc0 + 1)*8 + wid] = s1;
            partQ[(oc0    )*8 + wid] = q0;
            partQ[(oc0 + 1)*8 + wid] = q1;
        }
    }
    __syncthreads();
    if (tid < 128) {
        float S = 0.f, S2 = 0.f;
        #pragma unroll
        for (int w = 0; w < 8; w++) {
            S  += partS[tid*8 + w];
            S2 += partQ[tid*8 + w];
        }
        g_part [bid*OUTC_ + tid] = S;
        g_part2[bid*OUTC_ + tid] = S2;
    }
}

// ---------------------------------------------------------------------------
// Kernel 3a: reduce block partials -> mean/rstd
// ---------------------------------------------------------------------------
__global__ void __launch_bounds__(128) k_stats_final()
{
    const int oc = blockIdx.x;
    const int t  = threadIdx.x;
    float S = 0.f, S2 = 0.f;
    for (int i = t; i < NBLK_MAIN_; i += 128) {
        S  += g_part [i*OUTC_ + oc];
        S2 += g_part2[i*OUTC_ + oc];
    }
    __shared__ float sh[128], sh2[128];
    sh[t] = S; sh2[t] = S2;
    __syncthreads();
    for (int st = 64; st > 0; st >>= 1) {
        if (t < st) { sh[t] += sh[t + st]; sh2[t] += sh2[t + st]; }
        __syncthreads();
    }
    if (t == 0) {
        float mean = sh[0] / (float)REDN_;
        float var  = sh2[0] / (float)REDN_ - mean*mean;
        g_mean[oc] = mean;
        g_rstd[oc] = rsqrtf(var + 1e-5f);
    }
}

// ---------------------------------------------------------------------------
// Kernel 3b: BN affine + SiLU -> d_out (float4 vectorized)
// ---------------------------------------------------------------------------
__global__ void __launch_bounds__(256) k_bn_silu(
    const float* __restrict__ gamma,
    const float* __restrict__ beta,
    float* __restrict__ out)
{
    const int q = blockIdx.x * 256 + threadIdx.x;
    const int idx = q * 4;
    const int o = (idx / DHW_) & (OUTC_ - 1);
    const float m = g_mean[o];
    const float sg = g_rstd[o] * __ldg(&gamma[o]);
    const float bt = __ldg(&beta[o]);
    float4 v = *reinterpret_cast<const float4*>(&g_out[idx]);
    float4 r;
    {
        float y = (v.x - m) * sg + bt; r.x = y / (1.f + __expf(-y));
        y = (v.y - m) * sg + bt;       r.y = y / (1.f + __expf(-y));
        y = (v.z - m) * sg + bt;       r.z = y / (1.f + __expf(-y));
        y = (v.w - m) * sg + bt;       r.w = y / (1.f + __expf(-y));
    }
    *reinterpret_cast<float4*>(&out[idx]) = r;
}

// ---------------------------------------------------------------------------
extern "C" void kernel_launch(void* const* d_in, const int* in_sizes, int n_in,
                              void* d_out, int out_size)
{
    const float* x      = (const float*)d_in[0];
    const float* w_p    = (const float*)d_in[1];
    const float* b_p    = (const float*)d_in[2];
    const float* w_conv = (const float*)d_in[3];
    const float* gamma  = (const float*)d_in[4];
    const float* beta   = (const float*)d_in[5];
    float* out = (float*)d_out;

    cudaFuncSetAttribute(k_main, cudaFuncAttributeMaxDynamicSharedMemorySize, SMEM_MAIN_);

    k_wp<<<(INC_*27*OFFC_ + 255)/256, 256>>>(w_p);             // 162 blocks
    k_big<<<288 + 864 + 256, 288>>>(x, b_p, w_conv);           // offset + prep overlapped
    k_main<<<NBLK_MAIN_, 256, SMEM_MAIN_>>>();                 // 432 blocks
    k_stats_final<<<OUTC_, 128>>>();                           // 128 blocks
    k_bn_silu<<<B_*OUTC_*DHW_/1024, 256>>>(gamma, beta, out);  // 6912 blocks
}

// round 17
// speedup vs baseline: 1.1293x; 1.1293x over previous
#include <cuda_runtime.h>
#include <cuda_bf16.h>
#include <cstdint>

// Problem constants
#define B_   2
#define INC_ 64
#define OUTC_ 128
#define NP_  8
#define D_   12
#define H_   48
#define W_   48
#define HW_   (H_*W_)        // 2304
#define DHW_  (D_*HW_)       // 27648
#define OFFC_ (3*NP_)        // 24
#define REDN_ (B_*DHW_)      // 55296
#define POSBLK_ 128
#define NBLK_MAIN_ (B_*D_*(HW_/POSBLK_))   // 432
#define OFFTOT_ (B_*OFFC_*DHW_)

// Scratch (device globals; no allocations allowed)
__device__ float g_offp[2*OFFTOT_];                  // split-K offset partials
__device__ float g_out[B_*OUTC_*DHW_];               // ~28.3 MB
__device__ __nv_bfloat16 g_wtb_hi[NP_*INC_*OUTC_];   // [nn][c][oc] bf16 hi
__device__ __nv_bfloat16 g_wtb_lo[NP_*INC_*OUTC_];   // [nn][c][oc] bf16 lo
__device__ float g_wp[INC_*27*OFFC_];                // w_p -> [c][k][oc]
__device__ float g_xt[B_*DHW_*INC_];                 // x channel-last [b][dhw][c]
__device__ float g_part[NBLK_MAIN_*OUTC_];
__device__ float g_part2[NBLK_MAIN_*OUTC_];
__device__ float g_mean[OUTC_];
__device__ float g_rstd[OUTC_];

// _p_n(8): base=3, dep=2, row=1, mod=2
__device__ __constant__ float c_pnz[8] = {0,0,0,1,1,1,2,2};
__device__ __constant__ float c_pnx[8] = {0,0,0,0,0,0,1,1};
__device__ __constant__ float c_pny[8] = {0,1,2,0,1,2,0,1};

// ---------------- f32x2 helpers (offset conv: FFMA2, fp32-exact) ----------------
typedef unsigned long long u64;

__device__ __forceinline__ void ffma2(u64 &d, u64 a, u64 b) {
    asm("fma.rn.f32x2 %0, %1, %2, %0;" : "+l"(d) : "l"(a), "l"(b));
}
__device__ __forceinline__ u64 dup2(float x) {
    u64 r; asm("mov.b64 %0, {%1, %1};" : "=l"(r) : "f"(x)); return r;
}
__device__ __forceinline__ u64 pack2(float lo, float hi) {
    u64 r; asm("mov.b64 %0, {%1, %2};" : "=l"(r) : "f"(lo), "f"(hi)); return r;
}
__device__ __forceinline__ float lo32(u64 v){ return __uint_as_float((unsigned int)v); }
__device__ __forceinline__ float hi32(u64 v){ return __uint_as_float((unsigned int)(v >> 32)); }

// ---------------- mma.sync helpers (baseline sm_80+ ISA) ----------------
__device__ __forceinline__ uint32_t smem_u32(const void* p) {
    uint32_t a;
    asm("{ .reg .u64 t; cvta.to.shared.u64 t, %1; cvt.u32.u64 %0, t; }" : "=r"(a) : "l"(p));
    return a;
}
#define LDSM_X4(r0,r1,r2,r3, addr) \
    asm volatile("ldmatrix.sync.aligned.m8n8.x4.shared.b16 {%0,%1,%2,%3}, [%4];" \
        : "=r"(r0),"=r"(r1),"=r"(r2),"=r"(r3) : "r"(addr))
#define LDSM_X4T(r0,r1,r2,r3, addr) \
    asm volatile("ldmatrix.sync.aligned.m8n8.x4.trans.shared.b16 {%0,%1,%2,%3}, [%4];" \
        : "=r"(r0),"=r"(r1),"=r"(r2),"=r"(r3) : "r"(addr))
#define MMA_BF16(c, a0,a1,a2,a3, b0,b1) \
    asm volatile("mma.sync.aligned.m16n8k16.row.col.f32.bf16.bf16.f32 " \
        "{%0,%1,%2,%3}, {%4,%5,%6,%7}, {%8,%9}, {%0,%1,%2,%3};" \
        : "+f"((c)[0]),"+f"((c)[1]),"+f"((c)[2]),"+f"((c)[3]) \
        : "r"(a0),"r"(a1),"r"(a2),"r"(a3), "r"(b0),"r"(b1))

// SMEM layout for k_main (dynamic): total 104448 B
#define SM_IDX   0
#define SM_GWT   16384
#define SM_A_HI  32768
#define SM_A_LO  51200
#define SM_B_HI  69632
#define SM_B_LO  87040
#define SMEM_MAIN_ 104448
#define A_STRIDE_B 144
#define B_STRIDE_B 272

// ---------------------------------------------------------------------------
// Kernel PREP (merged homogeneous copies; proven R14 form):
//   [0,864) x transpose, [864,1120) w_conv bf16 split, [1120,1282) w_p transpose
// ---------------------------------------------------------------------------
__global__ void __launch_bounds__(256) k_prep(
    const float* __restrict__ x,
    const float* __restrict__ w_conv,
    const float* __restrict__ w_p)
{
    __shared__ float tile[64][65];
    const int blk = blockIdx.x;
    const int tid = threadIdx.x;

    if (blk < 864) {
        const int b = blk / (DHW_/64);
        const int p0 = (blk % (DHW_/64)) * 64;
        for (int idx = tid; idx < 4096; idx += 256) {
            int c = idx >> 6, p = idx & 63;
            tile[c][p] = x[(b*INC_ + c)*DHW_ + p0 + p];
        }
        __syncthreads();
        for (int idx = tid; idx < 4096; idx += 256) {
            int p = idx >> 6, c = idx & 63;
            g_xt[(b*DHW_ + p0 + p)*INC_ + c] = tile[c][p];
        }
    } else if (blk < 1120) {
        int idx = (blk - 864) * 256 + tid;      // 65536 total
        int nn = idx & 7;
        int c  = (idx >> 3) & 63;
        int o  = idx >> 9;
        float w = w_conv[idx];
        __nv_bfloat16 h = __float2bfloat16(w);
        __nv_bfloat16 l = __float2bfloat16(w - __bfloat162float(h));
        g_wtb_hi[(nn*INC_ + c)*OUTC_ + o] = h;
        g_wtb_lo[(nn*INC_ + c)*OUTC_ + o] = l;
    } else {
        int idx = (blk - 1120) * 256 + tid;     // 41472 total
        if (idx < INC_*27*OFFC_) {
            int k  = idx % 27;
            int c  = (idx / 27) % INC_;
            int oc = idx / (27*INC_);
            g_wp[(c*27 + k)*OFFC_ + oc] = w_p[idx];
        }
    }
}

// ---------------------------------------------------------------------------
// Kernel 1: offset conv (3x3x3, pad 1), FFMA2 — R9 body, 2-way channel split-K.
// Grid 576: bid%288 spatial (R9 mapping), s = bid/288 chooses cc 0-3 / 4-7.
// Same thread shape (4oc x 4w), same cheap strip staging; splits stage
// DISJOINT channel chunks so total staging/LDS traffic is unchanged.
// ---------------------------------------------------------------------------
__global__ void __launch_bounds__(288) k_offset_conv(
    const float* __restrict__ x,
    const float* __restrict__ b_p)
{
    __shared__ float x_s[8*3*6*52];
    __shared__ float w_s[8*27*24];

    const int gbid = blockIdx.x;
    const int bid  = gbid % 288;        // spatial
    const int s    = gbid / 288;        // split half
    const int hblk = bid % (H_/4);
    const int d = (bid / (H_/4)) % D_;
    const int b = bid / ((H_/4)*D_);
    const int h0 = hblk * 4;
    const int tid = threadIdx.x;
    const int hh  = tid / 72;
    const int r   = tid % 72;
    const int ocg = r / 12;
    const int wq  = r % 12;

    const int combo = tid >> 1;
    const int halfS = tid & 1;
    const int sc  = combo / 18;
    const int srw = combo % 18;
    const int sdz = srw / 6;
    const int sdh = srw % 6;
    const int sgd = d + sdz - 1;
    const int sgh = h0 + sdh - 1;
    const bool rowok = ((unsigned)sgd < (unsigned)D_) && ((unsigned)sgh < (unsigned)H_);
    const int srowbase = combo * 52 + halfS * 26;
    const int wl0 = halfS * 26;

    u64 acc[2][4];
    if (s == 0) {
        u64 p0 = pack2(__ldg(&b_p[ocg*4+0]), __ldg(&b_p[ocg*4+1]));
        u64 p1 = pack2(__ldg(&b_p[ocg*4+2]), __ldg(&b_p[ocg*4+3]));
        #pragma unroll
        for (int i = 0; i < 4; i++) { acc[0][i] = p0; acc[1][i] = p1; }
    } else {
        #pragma unroll
        for (int i = 0; i < 4; i++) { acc[0][i] = 0ull; acc[1][i] = 0ull; }
    }

    for (int cc = s*4; cc < s*4 + 4; cc++) {
        __syncthreads();
        {
            const float* xrow = x + ((size_t)(b*INC_ + cc*8 + sc)*D_ + (rowok ? sgd : 0))*HW_
                                  + (rowok ? sgh : 0)*W_;
            if (rowok) {
                #pragma unroll 13
                for (int j = 0; j < 26; j++) {
                    const int gw = wl0 + j - 1;
                    x_s[srowbase + j] = ((unsigned)gw < (unsigned)W_) ? xrow[gw] : 0.f;
                }
            } else {
                #pragma unroll 13
                for (int j = 0; j < 26; j++) x_s[srowbase + j] = 0.f;
            }
        }
        {
            const float4* src = reinterpret_cast<const float4*>(g_wp + cc*5184);
            float4* dst = reinterpret_cast<float4*>(w_s);
            for (int i = tid; i < 1296; i += 288) dst[i] = __ldg(&src[i]);
        }
        __syncthreads();

        #pragma unroll 2
        for (int c = 0; c < 8; c++) {
            #pragma unroll
            for (int kz = 0; kz < 3; kz++)
            #pragma unroll
            for (int kx = 0; kx < 3; kx++) {
                const float* xb = &x_s[((c*3 + kz)*6 + hh + kx)*52 + wq*4];
                float4 xa = *reinterpret_cast<const float4*>(xb);
                float2 xc = *reinterpret_cast<const float2*>(xb + 4);
                u64 X[6] = { dup2(xa.x), dup2(xa.y), dup2(xa.z),
                             dup2(xa.w), dup2(xc.x), dup2(xc.y) };
                #pragma unroll
                for (int ky = 0; ky < 3; ky++) {
                    ulonglong2 Wv = *reinterpret_cast<const ulonglong2*>(
                        &w_s[(c*27 + kz*9 + kx*3 + ky)*24 + ocg*4]);
                    #pragma unroll
                    for (int i = 0; i < 4; i++) {
                        ffma2(acc[0][i], Wv.x, X[ky + i]);
                        ffma2(acc[1][i], Wv.y, X[ky + i]);
                    }
                }
            }
        }
    }

    const int h = h0 + hh;
    float* outb = g_offp + s*OFFTOT_;
    #pragma unroll
    for (int p = 0; p < 2; p++) {
        float4 vl = make_float4(lo32(acc[p][0]), lo32(acc[p][1]),
                                lo32(acc[p][2]), lo32(acc[p][3]));
        float4 vh = make_float4(hi32(acc[p][0]), hi32(acc[p][1]),
                                hi32(acc[p][2]), hi32(acc[p][3]));
        int oc0 = ocg*4 + p*2;
        *reinterpret_cast<float4*>(
            &outb[((b*OFFC_ + oc0    )*D_ + d)*HW_ + h*W_ + wq*4]) = vl;
        *reinterpret_cast<float4*>(
            &outb[((b*OFFC_ + oc0 + 1)*D_ + d)*HW_ + h*W_ + wq*4]) = vh;
    }
}

// ---------------------------------------------------------------------------
// Kernel 2: deformable gather + bf16 3-term mma.sync GEMM (R14 body; offsets
// now summed from the two split-K planes, R6-proven pattern).
// ---------------------------------------------------------------------------
__global__ void __launch_bounds__(256) k_main()
{
    extern __shared__ unsigned char smraw[];
    int*   idx_s = (int*)(smraw + SM_IDX);
    float* gwt_s = (float*)(smraw + SM_GWT);
    const uint32_t smb = smem_u32(smraw);

    const int bid = blockIdx.x;
    const int p0   = (bid % (HW_/POSBLK_)) * POSBLK_;
    const int slab = bid / (HW_/POSBLK_);
    const int d = slab % D_;
    const int b = slab / D_;
    const int tid = threadIdx.x;
    const int lane = tid & 31;
    const int wid  = tid >> 5;

    const int bD = b * DHW_;
    #pragma unroll
    for (int i = 0; i < 4; i++) {
        const int q = tid + 256*i;
        const int p = q & 127;
        const int n = q >> 7;
        const int pos = p0 + p;
        const int h = pos / W_;
        const int w = pos % W_;
        const int off_base = (b*OFFC_*D_ + d)*HW_ + pos;
        const float oz = g_offp[off_base + (n       )*DHW_]
                       + g_offp[OFFTOT_ + off_base + (n       )*DHW_];
        const float ox = g_offp[off_base + (NP_  + n)*DHW_]
                       + g_offp[OFFTOT_ + off_base + (NP_  + n)*DHW_];
        const float oy = g_offp[off_base + (2*NP_+ n)*DHW_]
                       + g_offp[OFFTOT_ + off_base + (2*NP_+ n)*DHW_];

        const float pz = oz + (float)d + c_pnz[n];
        const float px = ox + (float)h + c_pnx[n];
        const float py = oy + (float)w + c_pny[n];

        const float fz = floorf(pz), fx = floorf(px), fy = floorf(py);
        const float z0f = fminf(fmaxf(fz,       0.f), (float)(D_-1));
        const float z1f = fminf(fmaxf(fz + 1.f, 0.f), (float)(D_-1));
        const float x0f = fminf(fmaxf(fx,       0.f), (float)(H_-1));
        const float x1f = fminf(fmaxf(fx + 1.f, 0.f), (float)(H_-1));
        const float y0f = fminf(fmaxf(fy,       0.f), (float)(W_-1));
        const float y1f = fminf(fmaxf(fy + 1.f, 0.f), (float)(W_-1));
        const float pzc = fminf(fmaxf(pz, 0.f), (float)(D_-1));
        const float pxc = fminf(fmaxf(px, 0.f), (float)(H_-1));
        const float pyc = fminf(fmaxf(py, 0.f), (float)(W_-1));

        const float az = 1.f + (z0f - pzc), bz = 1.f - (z1f - pzc);
        const float ax = 1.f + (x0f - pxc), bx = 1.f - (x1f - pxc);
        const float ay = 1.f + (y0f - pyc), by = 1.f - (y1f - pyc);

        const int z0 = (int)z0f, z1 = (int)z1f;
        const int x0 = (int)x0f, x1 = (int)x1f;
        const int y0 = (int)y0f, y1 = (int)y1f;

        idx_s[q*4+0] = (bD + z0*HW_ + x0*W_ + y0)*INC_;
        idx_s[q*4+1] = (bD + z1*HW_ + x1*W_ + y1)*INC_;
        idx_s[q*4+2] = (bD + z0*HW_ + x1*W_ + y0)*INC_;
        idx_s[q*4+3] = (bD + z1*HW_ + x0*W_ + y1)*INC_;
        gwt_s[q*4+0] = az*ax*ay;
        gwt_s[q*4+1] = bz*bx*by;
        gwt_s[q*4+2] = az*bx*ay;
        gwt_s[q*4+3] = bz*ax*by;
    }

    float acc[16][4];
    #pragma unroll
    for (int t = 0; t < 16; t++)
        #pragma unroll
        for (int j = 0; j < 4; j++) acc[t][j] = 0.f;

    const int f    = lane & 15;
    const int half = lane >> 4;

    const uint32_t aRowOff = (uint32_t)((wid*16 + (lane & 15))*A_STRIDE_B
                                        + ((lane >> 4) << 3)*2);
    const int bKrow = (((lane >> 3) & 1) << 3) + (lane & 7);
    const int bNcol = (lane >> 4) << 3;

    for (int nn = 0; nn < 8; nn++) {
        __syncthreads();
        {
            const uint2* srcH = reinterpret_cast<const uint2*>(g_wtb_hi + nn*8192);
            const uint2* srcL = reinterpret_cast<const uint2*>(g_wtb_lo + nn*8192);
            #pragma unroll
            for (int j = 0; j < 8; j++) {
                const int q = tid + 256*j;
                const int c  = q >> 5;
                const int oq = q & 31;
                *reinterpret_cast<uint2*>(smraw + SM_B_HI + c*B_STRIDE_B + oq*8) = __ldg(&srcH[q]);
                *reinterpret_cast<uint2*>(smraw + SM_B_LO + c*B_STRIDE_B + oq*8) = __ldg(&srcL[q]);
            }
        }
        #pragma unroll 8
        for (int pp = 0; pp < 16; pp++) {
            const int p = wid*16 + pp;
            const int q4 = ((nn << 7) + p) << 2;
            const int   i0 = idx_s[q4 + half];
            const float g0 = gwt_s[q4 + half];
            const int   i1 = idx_s[q4 + half + 2];
            const float g1 = gwt_s[q4 + half + 2];
            const float4 v0 = __ldg((const float4*)(g_xt + i0 + 4*f));
            const float4 v1 = __ldg((const float4*)(g_xt + i1 + 4*f));
            float4 rv;
            rv.x = g0*v0.x + g1*v1.x;
            rv.y = g0*v0.y + g1*v1.y;
            rv.z = g0*v0.z + g1*v1.z;
            rv.w = g0*v0.w + g1*v1.w;
            rv.x += __shfl_xor_sync(0xffffffffu, rv.x, 16);
            rv.y += __shfl_xor_sync(0xffffffffu, rv.y, 16);
            rv.z += __shfl_xor_sync(0xffffffffu, rv.z, 16);
            rv.w += __shfl_xor_sync(0xffffffffu, rv.w, 16);
            if (half == 0) {
                __nv_bfloat16 hx = __float2bfloat16(rv.x);
                __nv_bfloat16 hy = __float2bfloat16(rv.y);
                __nv_bfloat16 hz = __float2bfloat16(rv.z);
                __nv_bfloat16 hw = __float2bfloat16(rv.w);
                __nv_bfloat16 lx = __float2bfloat16(rv.x - __bfloat162float(hx));
                __nv_bfloat16 ly = __float2bfloat16(rv.y - __bfloat162float(hy));
                __nv_bfloat16 lz = __float2bfloat16(rv.z - __bfloat162float(hz));
                __nv_bfloat16 lw = __float2bfloat16(rv.w - __bfloat162float(hw));
                uint2 hv, lv;
                hv.x = ((uint32_t)__bfloat16_as_ushort(hy) << 16) | __bfloat16_as_ushort(hx);
                hv.y = ((uint32_t)__bfloat16_as_ushort(hw) << 16) | __bfloat16_as_ushort(hz);
                lv.x = ((uint32_t)__bfloat16_as_ushort(ly) << 16) | __bfloat16_as_ushort(lx);
                lv.y = ((uint32_t)__bfloat16_as_ushort(lw) << 16) | __bfloat16_as_ushort(lz);
                *reinterpret_cast<uint2*>(smraw + SM_A_HI + p*A_STRIDE_B + 8*f) = hv;
                *reinterpret_cast<uint2*>(smraw + SM_A_LO + p*A_STRIDE_B + 8*f) = lv;
            }
        }
        __syncthreads();

        #pragma unroll
        for (int kk = 0; kk < 4; kk++) {
            uint32_t ah0,ah1,ah2,ah3, al0,al1,al2,al3;
            const uint32_t aAddr = smb + SM_A_HI + aRowOff + (uint32_t)(kk*32);
            LDSM_X4(ah0,ah1,ah2,ah3, aAddr);
            LDSM_X4(al0,al1,al2,al3, aAddr + (SM_A_LO - SM_A_HI));
            #pragma unroll
            for (int ng = 0; ng < 8; ng++) {
                uint32_t bh0,bh1,bh2,bh3, bl0,bl1,bl2,bl3;
                const uint32_t bAddr = smb + SM_B_HI
                    + (uint32_t)((kk*16 + bKrow)*B_STRIDE_B + (ng*16 + bNcol)*2);
                LDSM_X4T(bh0,bh1,bh2,bh3, bAddr);
                LDSM_X4T(bl0,bl1,bl2,bl3, bAddr + (SM_B_LO - SM_B_HI));
                MMA_BF16(acc[2*ng  ], ah0,ah1,ah2,ah3, bh0,bh1);
                MMA_BF16(acc[2*ng+1], ah0,ah1,ah2,ah3, bh2,bh3);
                MMA_BF16(acc[2*ng  ], al0,al1,al2,al3, bh0,bh1);
                MMA_BF16(acc[2*ng+1], al0,al1,al2,al3, bh2,bh3);
                MMA_BF16(acc[2*ng  ], ah0,ah1,ah2,ah3, bl0,bl1);
                MMA_BF16(acc[2*ng+1], ah0,ah1,ah2,ah3, bl2,bl3);
            }
        }
    }

    float* partS = (float*)(smraw);
    float* partQ = (float*)(smraw + 4096);
    const int pos_lo = p0 + wid*16 + (lane >> 2);
    #pragma unroll
    for (int j = 0; j < 16; j++) {
        const int oc0 = j*8 + (lane & 3)*2;
        const float c0 = acc[j][0], c1 = acc[j][1], c2 = acc[j][2], c3 = acc[j][3];
        g_out[((b*OUTC_ + oc0    )*D_ + d)*HW_ + pos_lo    ] = c0;
        g_out[((b*OUTC_ + oc0 + 1)*D_ + d)*HW_ + pos_lo    ] = c1;
        g_out[((b*OUTC_ + oc0    )*D_ + d)*HW_ + pos_lo + 8] = c2;
        g_out[((b*OUTC_ + oc0 + 1)*D_ + d)*HW_ + pos_lo + 8] = c3;
        float s0 = c0 + c2, s1 = c1 + c3;
        float q0 = c0*c0 + c2*c2, q1 = c1*c1 + c3*c3;
        #pragma unroll
        for (int st = 4; st < 32; st <<= 1) {
            s0 += __shfl_xor_sync(0xffffffffu, s0, st);
            s1 += __shfl_xor_sync(0xffffffffu, s1, st);
            q0 += __shfl_xor_sync(0xffffffffu, q0, st);
            q1 += __shfl_xor_sync(0xffffffffu, q1, st);
        }
        if ((lane >> 2) == 0) {
            partS[(oc0    )*8 + wid] = s0;
            partS[(oc0 + 1)*8 + wid] = s1;
            partQ[(oc0    )*8 + wid] = q0;
            partQ[(oc0 + 1)*8 + wid] = q1;
        }
    }
    __syncthreads();
    if (tid < 128) {
        float S = 0.f, S2 = 0.f;
        #pragma unroll
        for (int w = 0; w < 8; w++) {
            S  += partS[tid*8 + w];
            S2 += partQ[tid*8 + w];
        }
        g_part [bid*OUTC_ + tid] = S;
        g_part2[bid*OUTC_ + tid] = S2;
    }
}

// ---------------------------------------------------------------------------
// Kernel 3a: reduce block partials -> mean/rstd
// ---------------------------------------------------------------------------
__global__ void __launch_bounds__(128) k_stats_final()
{
    const int oc = blockIdx.x;
    const int t  = threadIdx.x;
    float S = 0.f, S2 = 0.f;
    for (int i = t; i < NBLK_MAIN_; i += 128) {
        S  += g_part [i*OUTC_ + oc];
        S2 += g_part2[i*OUTC_ + oc];
    }
    __shared__ float sh[128], sh2[128];
    sh[t] = S; sh2[t] = S2;
    __syncthreads();
    for (int st = 64; st > 0; st >>= 1) {
        if (t < st) { sh[t] += sh[t + st]; sh2[t] += sh2[t + st]; }
        __syncthreads();
    }
    if (t == 0) {
        float mean = sh[0] / (float)REDN_;
        float var  = sh2[0] / (float)REDN_ - mean*mean;
        g_mean[oc] = mean;
        g_rstd[oc] = rsqrtf(var + 1e-5f);
    }
}

// ---------------------------------------------------------------------------
// Kernel 3b: BN affine + SiLU -> d_out (float4 vectorized)
// ---------------------------------------------------------------------------
__global__ void __launch_bounds__(256) k_bn_silu(
    const float* __restrict__ gamma,
    const float* __restrict__ beta,
    float* __restrict__ out)
{
    const int q = blockIdx.x * 256 + threadIdx.x;
    const int idx = q * 4;
    const int o = (idx / DHW_) & (OUTC_ - 1);
    const float m = g_mean[o];
    const float sg = g_rstd[o] * __ldg(&gamma[o]);
    const float bt = __ldg(&beta[o]);
    float4 v = *reinterpret_cast<const float4*>(&g_out[idx]);
    float4 r;
    {
        float y = (v.x - m) * sg + bt; r.x = y / (1.f + __expf(-y));
        y = (v.y - m) * sg + bt;       r.y = y / (1.f + __expf(-y));
        y = (v.z - m) * sg + bt;       r.z = y / (1.f + __expf(-y));
        y = (v.w - m) * sg + bt;       r.w = y / (1.f + __expf(-y));
    }
    *reinterpret_cast<float4*>(&out[idx]) = r;
}

// ---------------------------------------------------------------------------
extern "C" void kernel_launch(void* const* d_in, const int* in_sizes, int n_in,
                              void* d_out, int out_size)
{
    const float* x      = (const float*)d_in[0];
    const float* w_p    = (const float*)d_in[1];
    const float* b_p    = (const float*)d_in[2];
    const float* w_conv = (const float*)d_in[3];
    const float* gamma  = (const float*)d_in[4];
    const float* beta   = (const float*)d_in[5];
    float* out = (float*)d_out;

    cudaFuncSetAttribute(k_main, cudaFuncAttributeMaxDynamicSharedMemorySize, SMEM_MAIN_);

    k_prep<<<864 + 256 + 162, 256>>>(x, w_conv, w_p);          // merged prep (R14)
    k_offset_conv<<<2*288, 288>>>(x, b_p);                     // split-K x 2
    k_main<<<NBLK_MAIN_, 256, SMEM_MAIN_>>>();                 // 432 blocks
    k_stats_final<<<OUTC_, 128>>>();                           // 128 blocks
    k_bn_silu<<<B_*OUTC_*DHW_/1024, 256>>>(gamma, beta, out);  // 6912 blocks
}